// round 2
// baseline (speedup 1.0000x reference)
#include <cuda_runtime.h>

// Problem constants: x1, x2 are [N, D] fp32, N=8192, D=1024 (row-major).
// ort = dot(colsum(x1), colsum(x2)) / (N*N)

static constexpr int D    = 1024;
static constexpr int D4   = D / 4;     // 256 float4 per row
static constexpr int NB   = 296;       // colsum grid (148 SMs * 2)

// Scratch (no device allocation allowed -> __device__ globals)
__device__ float  g_part1[NB * D];
__device__ float  g_part2[NB * D];
__device__ double g_acc;

// K1: per-block partial column sums. Each thread owns 4 consecutive columns
// (one float4), grid-strides over rows. Coalesced 128B loads per warp per array.
__global__ __launch_bounds__(256) void colsum_partials(
    const float4* __restrict__ x1,
    const float4* __restrict__ x2,
    int nrows)
{
    const int t = threadIdx.x;          // 0..255 -> float4 column index
    const int b = blockIdx.x;

    if (b == 0 && t == 0) g_acc = 0.0;  // zero the scalar accumulator for K2

    float4 a1 = make_float4(0.f, 0.f, 0.f, 0.f);
    float4 a2 = make_float4(0.f, 0.f, 0.f, 0.f);

    #pragma unroll 4
    for (int r = b; r < nrows; r += NB) {
        const size_t off = (size_t)r * D4 + t;
        const float4 v1 = __ldg(&x1[off]);
        const float4 v2 = __ldg(&x2[off]);
        a1.x += v1.x; a1.y += v1.y; a1.z += v1.z; a1.w += v1.w;
        a2.x += v2.x; a2.y += v2.y; a2.z += v2.z; a2.w += v2.w;
    }

    // Coalesced float4 store of this block's partial sums.
    ((float4*)g_part1)[(size_t)b * D4 + t] = a1;
    ((float4*)g_part2)[(size_t)b * D4 + t] = a2;
}

// K2: finish the column reduction over NB partials, then dot the two colsum
// vectors. 8 blocks x 256 threads; block handles 32 float4-columns (128 cols).
// Thread (j0 = t>>5, cv = t&31): sums partial rows j0, j0+8, ... for its
// column vector; shared-mem reduce across the 8 j-chunks; THEN multiply
// (product of completed sums), warp-reduce in double, one atomicAdd per block.
__global__ __launch_bounds__(256) void reduce_and_dot()
{
    __shared__ float4 sh1[8][32];
    __shared__ float4 sh2[8][32];

    const int t   = threadIdx.x;
    const int cvl = t & 31;                       // local float4-column 0..31
    const int j0  = t >> 5;                       // partial-row chunk 0..7
    const int cv  = blockIdx.x * 32 + cvl;        // global float4-column 0..255

    const float4* p1 = (const float4*)g_part1;
    const float4* p2 = (const float4*)g_part2;

    float4 s1 = make_float4(0.f, 0.f, 0.f, 0.f);
    float4 s2 = make_float4(0.f, 0.f, 0.f, 0.f);

    for (int j = j0; j < NB; j += 8) {
        const float4 v1 = p1[(size_t)j * D4 + cv];
        const float4 v2 = p2[(size_t)j * D4 + cv];
        s1.x += v1.x; s1.y += v1.y; s1.z += v1.z; s1.w += v1.w;
        s2.x += v2.x; s2.y += v2.y; s2.z += v2.z; s2.w += v2.w;
    }

    sh1[j0][cvl] = s1;
    sh2[j0][cvl] = s2;
    __syncthreads();

    if (j0 == 0) {
        // finish column sums across the 8 chunks
        #pragma unroll
        for (int j = 1; j < 8; j++) {
            const float4 v1 = sh1[j][cvl];
            const float4 v2 = sh2[j][cvl];
            s1.x += v1.x; s1.y += v1.y; s1.z += v1.z; s1.w += v1.w;
            s2.x += v2.x; s2.y += v2.y; s2.z += v2.z; s2.w += v2.w;
        }
        // dot contribution of these 4 columns, in double
        double d = (double)s1.x * (double)s2.x
                 + (double)s1.y * (double)s2.y
                 + (double)s1.z * (double)s2.z
                 + (double)s1.w * (double)s2.w;
        // warp reduce (warp 0 holds all 32 cv lanes since j0==0 -> t==cvl)
        #pragma unroll
        for (int off = 16; off > 0; off >>= 1)
            d += __shfl_down_sync(0xFFFFFFFFu, d, off);
        if (cvl == 0)
            atomicAdd(&g_acc, d);
    }
}

// K3: finalize scalar
__global__ void finalize(float* __restrict__ out, double inv_count)
{
    out[0] = (float)(g_acc * inv_count);
}

extern "C" void kernel_launch(void* const* d_in, const int* in_sizes, int n_in,
                              void* d_out, int out_size)
{
    const float4* x1 = (const float4*)d_in[0];
    const float4* x2 = (const float4*)d_in[1];
    float* out = (float*)d_out;

    const int rows1 = in_sizes[0] / D;   // 8192
    const int rows2 = in_sizes[1] / D;   // 8192
    const double inv_count = 1.0 / ((double)rows1 * (double)rows2);

    colsum_partials<<<NB, 256>>>(x1, x2, rows1);
    reduce_and_dot<<<8, 256>>>();
    finalize<<<1, 1>>>(out, inv_count);
}

// round 3
// speedup vs baseline: 1.2272x; 1.2272x over previous
#include <cuda_runtime.h>

// x1, x2: [N, D] fp32, N=8192, D=1024 row-major.
// ort = dot(colsum(x1), colsum(x2)) / (N*N)

static constexpr int D   = 1024;
static constexpr int D4  = D / 4;    // 256 float4 per row
static constexpr int NB  = 592;      // K1 grid = 148 SMs * 4

// Scratch (__device__ globals; no allocation allowed)
__device__ float    g_part1[NB * D];     // 2.42 MB
__device__ float    g_part2[NB * D];     // 2.42 MB
__device__ double   g_acc;
__device__ unsigned g_done;

__device__ __forceinline__ void acc4(float4& a, const float4 v) {
    a.x += v.x; a.y += v.y; a.z += v.z; a.w += v.w;
}

// ── K1: per-block partial column sums ──────────────────────────────────────
// Each thread owns one float4 column group, grid-strides over rows with a
// manual 4-row unroll: 8 independent LDG.128 issued back-to-back (MLP=8),
// accumulation only afterwards. 2 accumulators per array break the FADD chain.
__global__ __launch_bounds__(256, 4) void colsum_partials(
    const float4* __restrict__ x1,
    const float4* __restrict__ x2,
    int nrows)
{
    const int t = threadIdx.x;
    const int b = blockIdx.x;

    if (b == 0 && t == 0) { g_acc = 0.0; g_done = 0u; }  // reset for K2

    const size_t stride = (size_t)NB * D4;
    size_t off = (size_t)b * D4 + t;

    float4 a10 = make_float4(0.f,0.f,0.f,0.f), a11 = a10;
    float4 a20 = a10, a21 = a10;

    int r = b;
    // Main loop: 4 rows per iteration, 8 batched independent loads.
    for (; r + 3 * NB < nrows; r += 4 * NB, off += 4 * stride) {
        const float4 u0 = __ldg(x1 + off);
        const float4 u1 = __ldg(x1 + off +     stride);
        const float4 u2 = __ldg(x1 + off + 2 * stride);
        const float4 u3 = __ldg(x1 + off + 3 * stride);
        const float4 w0 = __ldg(x2 + off);
        const float4 w1 = __ldg(x2 + off +     stride);
        const float4 w2 = __ldg(x2 + off + 2 * stride);
        const float4 w3 = __ldg(x2 + off + 3 * stride);
        acc4(a10, u0); acc4(a11, u1); acc4(a10, u2); acc4(a11, u3);
        acc4(a20, w0); acc4(a21, w1); acc4(a20, w2); acc4(a21, w3);
    }
    // Remainder (0-3 rows)
    for (; r < nrows; r += NB, off += stride) {
        acc4(a10, __ldg(x1 + off));
        acc4(a20, __ldg(x2 + off));
    }

    acc4(a10, a11);
    acc4(a20, a21);
    ((float4*)g_part1)[(size_t)b * D4 + t] = a10;
    ((float4*)g_part2)[(size_t)b * D4 + t] = a20;
}

// ── K2: finish colsums, dot, finalize ──────────────────────────────────────
// 256 blocks, one float4 column each. Thread j sums partial rows j, j+256, ...
// (592 rows -> 2-3 loads per array per thread, all L2-resident). Block-reduce
// the COMPLETE column sums first, then multiply in double and atomicAdd.
// Last block to finish writes the scalar output (ticket via g_done).
__global__ __launch_bounds__(256) void reduce_dot_finalize(
    float* __restrict__ out, double inv_count)
{
    const int t  = threadIdx.x;
    const int cv = blockIdx.x;                 // float4 column 0..255

    const float4* p1 = (const float4*)g_part1;
    const float4* p2 = (const float4*)g_part2;

    float4 s1 = make_float4(0.f,0.f,0.f,0.f);
    float4 s2 = s1;
    for (int j = t; j < NB; j += 256) {
        acc4(s1, p1[(size_t)j * D4 + cv]);
        acc4(s2, p2[(size_t)j * D4 + cv]);
    }

    // warp reduce (all 8 components)
    #pragma unroll
    for (int o = 16; o > 0; o >>= 1) {
        s1.x += __shfl_down_sync(0xFFFFFFFFu, s1.x, o);
        s1.y += __shfl_down_sync(0xFFFFFFFFu, s1.y, o);
        s1.z += __shfl_down_sync(0xFFFFFFFFu, s1.z, o);
        s1.w += __shfl_down_sync(0xFFFFFFFFu, s1.w, o);
        s2.x += __shfl_down_sync(0xFFFFFFFFu, s2.x, o);
        s2.y += __shfl_down_sync(0xFFFFFFFFu, s2.y, o);
        s2.z += __shfl_down_sync(0xFFFFFFFFu, s2.z, o);
        s2.w += __shfl_down_sync(0xFFFFFFFFu, s2.w, o);
    }

    __shared__ float4 sh1[8], sh2[8];
    const int warp = t >> 5, lane = t & 31;
    if (lane == 0) { sh1[warp] = s1; sh2[warp] = s2; }
    __syncthreads();

    if (warp == 0) {
        float4 r1 = (lane < 8) ? sh1[lane] : make_float4(0.f,0.f,0.f,0.f);
        float4 r2 = (lane < 8) ? sh2[lane] : make_float4(0.f,0.f,0.f,0.f);
        #pragma unroll
        for (int o = 4; o > 0; o >>= 1) {
            r1.x += __shfl_down_sync(0xFFFFFFFFu, r1.x, o);
            r1.y += __shfl_down_sync(0xFFFFFFFFu, r1.y, o);
            r1.z += __shfl_down_sync(0xFFFFFFFFu, r1.z, o);
            r1.w += __shfl_down_sync(0xFFFFFFFFu, r1.w, o);
            r2.x += __shfl_down_sync(0xFFFFFFFFu, r2.x, o);
            r2.y += __shfl_down_sync(0xFFFFFFFFu, r2.y, o);
            r2.z += __shfl_down_sync(0xFFFFFFFFu, r2.z, o);
            r2.w += __shfl_down_sync(0xFFFFFFFFu, r2.w, o);
        }
        if (lane == 0) {
            // COMPLETE column sums for these 4 columns -> dot in double
            const double d = (double)r1.x * (double)r2.x
                           + (double)r1.y * (double)r2.y
                           + (double)r1.z * (double)r2.z
                           + (double)r1.w * (double)r2.w;
            atomicAdd(&g_acc, d);
            __threadfence();
            const unsigned ticket = atomicAdd(&g_done, 1u);
            if (ticket == gridDim.x - 1) {
                const double total = *((volatile double*)&g_acc);
                out[0] = (float)(total * inv_count);
            }
        }
    }
}

extern "C" void kernel_launch(void* const* d_in, const int* in_sizes, int n_in,
                              void* d_out, int out_size)
{
    const float4* x1 = (const float4*)d_in[0];
    const float4* x2 = (const float4*)d_in[1];
    float* out = (float*)d_out;

    const int rows1 = in_sizes[0] / D;   // 8192
    const int rows2 = in_sizes[1] / D;   // 8192
    const double inv_count = 1.0 / ((double)rows1 * (double)rows2);

    colsum_partials<<<NB, 256>>>(x1, x2, rows1);
    reduce_dot_finalize<<<D4, 256>>>(out, inv_count);
}